// round 2
// baseline (speedup 1.0000x reference)
#include <cuda_runtime.h>

#define NN 20000
#define EE 320000
#define DD 256

// ---------------- scratch (static device globals; no allocation) ----------
__device__ float g_h [NN * DD];   // node features between layers
__device__ float g_xl[NN * DD];   // h @ Wl
__device__ float g_xr[NN * DD];   // h @ Wr
__device__ int   g_deg[NN];
__device__ int   g_rowptr[NN + 1];
__device__ int   g_wptr[NN];
__device__ int   g_col[EE];       // src indices sorted by dst (CSR)

// ---------------- CSR build ----------------------------------------------
__global__ void zero_deg_kernel(int n) {
    int i = blockIdx.x * blockDim.x + threadIdx.x;
    if (i < n) g_deg[i] = 0;
}

__global__ void hist_kernel(const int* __restrict__ ei, int E) {
    int e = blockIdx.x * blockDim.x + threadIdx.x;
    if (e < E) atomicAdd(&g_deg[ei[E + e]], 1);   // ei[1][e] = dst
}

// single-block exclusive scan: g_rowptr[0]=0, g_rowptr[i+1]=sum deg[0..i]
__global__ void scan_kernel(int n) {
    __shared__ int sh[1024];
    __shared__ int carry;
    int t = threadIdx.x;
    if (t == 0) { carry = 0; g_rowptr[0] = 0; }
    __syncthreads();
    for (int base = 0; base < n; base += 1024) {
        int i = base + t;
        int v = (i < n) ? g_deg[i] : 0;
        sh[t] = v;
        __syncthreads();
        for (int off = 1; off < 1024; off <<= 1) {
            int tv = (t >= off) ? sh[t - off] : 0;
            __syncthreads();
            sh[t] += tv;
            __syncthreads();
        }
        if (i < n) g_rowptr[i + 1] = carry + sh[t];
        __syncthreads();
        if (t == 0) carry += sh[1023];
        __syncthreads();
    }
}

__global__ void wptr_kernel(int n) {
    int i = blockIdx.x * blockDim.x + threadIdx.x;
    if (i < n) g_wptr[i] = g_rowptr[i];
}

__global__ void scatter_kernel(const int* __restrict__ ei, int E) {
    int e = blockIdx.x * blockDim.x + threadIdx.x;
    if (e < E) {
        int dst = ei[E + e];
        int pos = atomicAdd(&g_wptr[dst], 1);
        g_col[pos] = ei[e];                        // ei[0][e] = src
    }
}

// ---------------- SGEMM: C[M,256] = A[M,256] @ W[256,256] -----------------
// 64x64 tile, BK=16, 256 threads, 4x4 per thread, float4 global loads.
// a_ext: if nonzero use A_ext as input, else g_h. out_sel: 0->g_xl, 1->g_xr.
__global__ void __launch_bounds__(256)
sgemm_kernel(const float* __restrict__ A_ext, int a_ext,
             const float* __restrict__ W, int out_sel, int M) {
    __shared__ float As[16][68];
    __shared__ float Ws[16][68];

    const float* __restrict__ A = a_ext ? A_ext : g_h;
    float* __restrict__ C = out_sel ? g_xr : g_xl;

    int tid = threadIdx.x;
    int tx = tid & 15, ty = tid >> 4;
    int rowBase = blockIdx.y << 6;
    int colBase = blockIdx.x << 6;

    float acc[4][4];
#pragma unroll
    for (int i = 0; i < 4; i++)
#pragma unroll
        for (int j = 0; j < 4; j++) acc[i][j] = 0.f;

    for (int k0 = 0; k0 < DD; k0 += 16) {
        // A tile: 64 rows x 16 k (transposed into As[k][m])
        {
            int m  = tid >> 2;
            int kq = (tid & 3) << 2;
            int row = rowBase + m;
            float4 av = (row < M)
                ? *(const float4*)&A[row * DD + k0 + kq]
                : make_float4(0.f, 0.f, 0.f, 0.f);
            As[kq + 0][m] = av.x;
            As[kq + 1][m] = av.y;
            As[kq + 2][m] = av.z;
            As[kq + 3][m] = av.w;
        }
        // W tile: 16 k x 64 n
        {
            int kk = tid >> 4;
            int nq = (tid & 15) << 2;
            *(float4*)&Ws[kk][nq] =
                *(const float4*)&W[(k0 + kk) * DD + colBase + nq];
        }
        __syncthreads();
#pragma unroll
        for (int k = 0; k < 16; k++) {
            float a0 = As[k][(ty << 2) + 0];
            float a1 = As[k][(ty << 2) + 1];
            float a2 = As[k][(ty << 2) + 2];
            float a3 = As[k][(ty << 2) + 3];
            float4 wv = *(const float4*)&Ws[k][tx << 2];
            acc[0][0] += a0 * wv.x; acc[0][1] += a0 * wv.y;
            acc[0][2] += a0 * wv.z; acc[0][3] += a0 * wv.w;
            acc[1][0] += a1 * wv.x; acc[1][1] += a1 * wv.y;
            acc[1][2] += a1 * wv.z; acc[1][3] += a1 * wv.w;
            acc[2][0] += a2 * wv.x; acc[2][1] += a2 * wv.y;
            acc[2][2] += a2 * wv.z; acc[2][3] += a2 * wv.w;
            acc[3][0] += a3 * wv.x; acc[3][1] += a3 * wv.y;
            acc[3][2] += a3 * wv.z; acc[3][3] += a3 * wv.w;
        }
        __syncthreads();
    }
#pragma unroll
    for (int i = 0; i < 4; i++) {
        int row = rowBase + (ty << 2) + i;
        if (row < M)
            *(float4*)&C[row * DD + colBase + (tx << 2)] =
                make_float4(acc[i][0], acc[i][1], acc[i][2], acc[i][3]);
    }
}

// ---------------- fused GATv2 aggregate + bias + LayerNorm + ReLU ---------
// One block per destination node. Warp h handles head h (C=64 channels,
// 2 per lane). Online softmax over incoming edges + 1 implicit self loop.
__global__ void __launch_bounds__(128)
gat_agg_kernel(const float* __restrict__ att, const float* __restrict__ bias,
               const float* __restrict__ gamma, const float* __restrict__ beta,
               float* __restrict__ ext_out, int write_ext) {
    int dst  = blockIdx.x;
    int warp = threadIdx.x >> 5;
    int lane = threadIdx.x & 31;
    int c0   = (warp << 6) + (lane << 1);     // flat channel index (head*64 + c)

    float2 xrv  = *(const float2*)&g_xr[dst * DD + c0];
    float2 attv = *(const float2*)&att[c0];

    float m = -1e30f, lsum = 0.f;
    float accx = 0.f, accy = 0.f;

    int start = g_rowptr[dst];
    int end   = g_rowptr[dst + 1];
    for (int e = start - 1; e < end; e++) {
        int src = (e < start) ? dst : g_col[e];      // e==start-1 -> self loop
        float2 xv = *(const float2*)&g_xl[src * DD + c0];
        float ax = xv.x + xrv.x;
        float ay = xv.y + xrv.y;
        ax = (ax > 0.f) ? ax : 0.2f * ax;            // leaky relu
        ay = (ay > 0.f) ? ay : 0.2f * ay;
        float s = ax * attv.x + ay * attv.y;
#pragma unroll
        for (int off = 16; off; off >>= 1)
            s += __shfl_xor_sync(0xffffffffu, s, off);
        float nm = fmaxf(m, s);
        float sc = __expf(m - nm);
        float p  = __expf(s - nm);
        accx = accx * sc + p * xv.x;
        accy = accy * sc + p * xv.y;
        lsum = lsum * sc + p;
        m = nm;
    }
    float inv_l = 1.0f / lsum;
    float ox = accx * inv_l + bias[c0];
    float oy = accy * inv_l + bias[c0 + 1];

    // LayerNorm over all 256 channels of this node
    float s1 = ox + oy;
    float s2 = ox * ox + oy * oy;
#pragma unroll
    for (int off = 16; off; off >>= 1) {
        s1 += __shfl_xor_sync(0xffffffffu, s1, off);
        s2 += __shfl_xor_sync(0xffffffffu, s2, off);
    }
    __shared__ float sh1[4], sh2[4];
    if (lane == 0) { sh1[warp] = s1; sh2[warp] = s2; }
    __syncthreads();
    s1 = sh1[0] + sh1[1] + sh1[2] + sh1[3];
    s2 = sh2[0] + sh2[1] + sh2[2] + sh2[3];
    float mean = s1 * (1.0f / DD);
    float var  = s2 * (1.0f / DD) - mean * mean;
    float rinv = rsqrtf(var + 1e-5f);

    ox = (ox - mean) * rinv * gamma[c0]     + beta[c0];
    oy = (oy - mean) * rinv * gamma[c0 + 1] + beta[c0 + 1];
    ox = fmaxf(ox, 0.f);
    oy = fmaxf(oy, 0.f);

    float* __restrict__ out = write_ext ? ext_out : g_h;
    *(float2*)&out[dst * DD + c0] = make_float2(ox, oy);
}

// ---------------- launch ---------------------------------------------------
extern "C" void kernel_launch(void* const* d_in, const int* in_sizes, int n_in,
                              void* d_out, int out_size) {
    const float* x  = (const float*)d_in[0];
    const int*   ei = (const int*)d_in[1];
    int E = in_sizes[1] / 2;          // 320000
    int N = in_sizes[0] / DD;         // 20000
    float* out = (float*)d_out;

    // CSR build (same result every call; atomic order only affects fp
    // summation order inside tolerance)
    zero_deg_kernel<<<(N + 255) / 256, 256>>>(N);
    hist_kernel<<<(E + 255) / 256, 256>>>(ei, E);
    scan_kernel<<<1, 1024>>>(N);
    wptr_kernel<<<(N + 255) / 256, 256>>>(N);
    scatter_kernel<<<(E + 255) / 256, 256>>>(ei, E);

    dim3 ggrid(DD / 64, (N + 63) / 64);

    for (int layer = 0; layer < 4; layer++) {
        const float* Wl  = (const float*)d_in[2 + 6 * layer + 0];
        const float* Wr  = (const float*)d_in[2 + 6 * layer + 1];
        const float* att = (const float*)d_in[2 + 6 * layer + 2];
        const float* b   = (const float*)d_in[2 + 6 * layer + 3];
        const float* g   = (const float*)d_in[2 + 6 * layer + 4];
        const float* be  = (const float*)d_in[2 + 6 * layer + 5];

        int first = (layer == 0);
        sgemm_kernel<<<ggrid, 256>>>(x, first, Wl, 0, N);   // -> g_xl
        sgemm_kernel<<<ggrid, 256>>>(x, first, Wr, 1, N);   // -> g_xr
        int last = (layer == 3);
        gat_agg_kernel<<<N, 128>>>(att, b, g, be, out, last);
    }
}

// round 4
// speedup vs baseline: 1.6341x; 1.6341x over previous
#include <cuda_runtime.h>
#include <cuda_bf16.h>
#include <cstdint>

#define NN 20000
#define EE 320000
#define DD 256

// ---------------- scratch (static device globals; no allocation) ----------
__device__ float g_h [NN * DD];   // node features between layers
__device__ float g_xl[NN * DD];   // h @ Wl
__device__ float g_xr[NN * DD];   // h @ Wr
__device__ int   g_deg[NN];
__device__ int   g_rowptr[NN + 1];
__device__ int   g_wptr[NN];
__device__ int   g_col[EE];       // src indices sorted by dst (CSR)

// transposed, bf16-split weights: Wt[n][k] = W[k][n]
__device__ __nv_bfloat16 g_WtLh[DD * DD];
__device__ __nv_bfloat16 g_WtLl[DD * DD];
__device__ __nv_bfloat16 g_WtRh[DD * DD];
__device__ __nv_bfloat16 g_WtRl[DD * DD];

// ---------------- helpers ---------------------------------------------------
__device__ __forceinline__ uint32_t smem_u32(const void* p) {
    uint32_t a;
    asm("{ .reg .u64 t; cvta.to.shared.u64 t, %1; cvt.u32.u64 %0, t; }"
        : "=r"(a) : "l"(p));
    return a;
}
#define SWZ(o) ((o) ^ (((o) >> 3) & 0x70))

#define LDSM_X4(r0, r1, r2, r3, a)                                          \
    asm volatile("ldmatrix.sync.aligned.m8n8.x4.shared.b16 {%0,%1,%2,%3}, [%4];" \
                 : "=r"(r0), "=r"(r1), "=r"(r2), "=r"(r3) : "r"(a))

#define MMA_BF16(d, a, b)                                                   \
    asm volatile("mma.sync.aligned.m16n8k16.row.col.f32.bf16.bf16.f32 "     \
                 "{%0,%1,%2,%3}, {%4,%5,%6,%7}, {%8,%9}, {%0,%1,%2,%3};"    \
                 : "+f"((d)[0]), "+f"((d)[1]), "+f"((d)[2]), "+f"((d)[3])   \
                 : "r"((a)[0]), "r"((a)[1]), "r"((a)[2]), "r"((a)[3]),      \
                   "r"((b)[0]), "r"((b)[1]))

// ---------------- CSR build ----------------------------------------------
__global__ void zero_deg_kernel(int n) {
    int i = blockIdx.x * blockDim.x + threadIdx.x;
    if (i < n) g_deg[i] = 0;
}
__global__ void hist_kernel(const int* __restrict__ ei, int E) {
    int e = blockIdx.x * blockDim.x + threadIdx.x;
    if (e < E) atomicAdd(&g_deg[ei[E + e]], 1);
}
__global__ void scan_kernel(int n) {
    __shared__ int sh[1024];
    __shared__ int carry;
    int t = threadIdx.x;
    if (t == 0) { carry = 0; g_rowptr[0] = 0; }
    __syncthreads();
    for (int base = 0; base < n; base += 1024) {
        int i = base + t;
        int v = (i < n) ? g_deg[i] : 0;
        sh[t] = v;
        __syncthreads();
        for (int off = 1; off < 1024; off <<= 1) {
            int tv = (t >= off) ? sh[t - off] : 0;
            __syncthreads();
            sh[t] += tv;
            __syncthreads();
        }
        if (i < n) g_rowptr[i + 1] = carry + sh[t];
        __syncthreads();
        if (t == 0) carry += sh[1023];
        __syncthreads();
    }
}
__global__ void wptr_kernel(int n) {
    int i = blockIdx.x * blockDim.x + threadIdx.x;
    if (i < n) g_wptr[i] = g_rowptr[i];
}
__global__ void scatter_kernel(const int* __restrict__ ei, int E) {
    int e = blockIdx.x * blockDim.x + threadIdx.x;
    if (e < E) {
        int dst = ei[E + e];
        int pos = atomicAdd(&g_wptr[dst], 1);
        g_col[pos] = ei[e];
    }
}

// ---------------- weight transpose + bf16 hi/lo split ----------------------
__global__ void prep_w_kernel(const float* __restrict__ Wl,
                              const float* __restrict__ Wr) {
    __shared__ float t[32][33];
    const float* W = blockIdx.z ? Wr : Wl;
    __nv_bfloat16* Oh = blockIdx.z ? g_WtRh : g_WtLh;
    __nv_bfloat16* Ol = blockIdx.z ? g_WtRl : g_WtLl;
    int bx = blockIdx.x * 32, by = blockIdx.y * 32;
    int tx = threadIdx.x, ty = threadIdx.y;       // 32 x 8
#pragma unroll
    for (int i = 0; i < 32; i += 8)
        t[ty + i][tx] = W[(by + ty + i) * DD + bx + tx];
    __syncthreads();
#pragma unroll
    for (int i = 0; i < 32; i += 8) {
        float v = t[tx][ty + i];
        __nv_bfloat16 h = __float2bfloat16_rn(v);
        __nv_bfloat16 l = __float2bfloat16_rn(v - __bfloat162float(h));
        int n = bx + ty + i, k = by + tx;
        Oh[n * DD + k] = h;
        Ol[n * DD + k] = l;
    }
}

// ---------------- mma.sync bf16x3 GEMM -------------------------------------
// C[M,512] = A[M,256] @ [Wl | Wr]  (fp32-accurate via hi/lo bf16 split).
// CTA: 128 rows x 128 cols, 8 warps (2 x 4), warp tile 64x32, K chunk 64.
// Smem (dynamic, 64KB): A_hi 16K | A_lo 16K | B_hi 16K | B_lo 16K, SW128.
#define SA_H 0
#define SA_L 16384
#define SB_H 32768
#define SB_L 49152
#define GEMM_SMEM 65536

__global__ void __launch_bounds__(256, 1)
gemm_kernel(const float* __restrict__ Aext, int use_ext, int M) {
    extern __shared__ char smem[];
    uint32_t sb = smem_u32(smem);
    const float* __restrict__ A = use_ext ? Aext : g_h;

    int tid = threadIdx.x;
    int lane = tid & 31, wid = tid >> 5;
    int warpM = wid >> 2, warpN = wid & 3;
    int rowBase = blockIdx.y << 7;
    int colBase = blockIdx.x << 7;         // 0..511 in steps of 128

    const __nv_bfloat16* __restrict__ Bh = (colBase < 256) ? g_WtLh : g_WtRh;
    const __nv_bfloat16* __restrict__ Bl = (colBase < 256) ? g_WtLl : g_WtRl;
    int nBase = colBase & 255;             // row offset into Wt

    float acc[4][4][4];
#pragma unroll
    for (int i = 0; i < 4; i++)
#pragma unroll
        for (int j = 0; j < 4; j++)
#pragma unroll
            for (int q = 0; q < 4; q++) acc[i][j][q] = 0.f;

    // per-thread ldmatrix byte offsets (before swizzle, before kk*32)
    uint32_t aOff[4], bOff[2];
#pragma unroll
    for (int im = 0; im < 4; im++)
        aOff[im] = (uint32_t)((warpM * 64 + im * 16 + (lane & 15)) * 128 +
                              (lane >> 4) * 16);
#pragma unroll
    for (int ip = 0; ip < 2; ip++)
        bOff[ip] = (uint32_t)((warpN * 32 + ip * 16 + ((lane >> 4) & 1) * 8 +
                               (lane & 7)) * 128 + ((lane >> 3) & 1) * 16);

    for (int ch = 0; ch < 4; ch++) {
        int k0 = ch << 6;
        // ---- A tile: 128 rows x 64 k, fp32 -> bf16 hi/lo on the fly ----
#pragma unroll
        for (int it = 0; it < 8; it++) {
            int t2 = it * 256 + tid;
            int k4 = t2 & 15;
            int row = t2 >> 4;
            float4 v = make_float4(0.f, 0.f, 0.f, 0.f);
            if (rowBase + row < M)
                v = *(const float4*)&A[(rowBase + row) * DD + k0 + 4 * k4];
            __nv_bfloat16 h0 = __float2bfloat16_rn(v.x);
            __nv_bfloat16 h1 = __float2bfloat16_rn(v.y);
            __nv_bfloat16 h2 = __float2bfloat16_rn(v.z);
            __nv_bfloat16 h3 = __float2bfloat16_rn(v.w);
            __nv_bfloat16 l0 = __float2bfloat16_rn(v.x - __bfloat162float(h0));
            __nv_bfloat16 l1 = __float2bfloat16_rn(v.y - __bfloat162float(h1));
            __nv_bfloat16 l2 = __float2bfloat16_rn(v.z - __bfloat162float(h2));
            __nv_bfloat16 l3 = __float2bfloat16_rn(v.w - __bfloat162float(h3));
            uint32_t hp0 = (uint32_t)__bfloat16_as_ushort(h0) |
                           ((uint32_t)__bfloat16_as_ushort(h1) << 16);
            uint32_t hp1 = (uint32_t)__bfloat16_as_ushort(h2) |
                           ((uint32_t)__bfloat16_as_ushort(h3) << 16);
            uint32_t lp0 = (uint32_t)__bfloat16_as_ushort(l0) |
                           ((uint32_t)__bfloat16_as_ushort(l1) << 16);
            uint32_t lp1 = (uint32_t)__bfloat16_as_ushort(l2) |
                           ((uint32_t)__bfloat16_as_ushort(l3) << 16);
            uint32_t off = SWZ((uint32_t)(row * 128 + 8 * k4));
            *(uint2*)(smem + SA_H + off) = make_uint2(hp0, hp1);
            *(uint2*)(smem + SA_L + off) = make_uint2(lp0, lp1);
        }
        // ---- B tiles: 128 n x 64 k bf16 (hi and lo), 16B vectorized ----
#pragma unroll
        for (int it = 0; it < 4; it++) {
            int t2 = it * 256 + tid;
            int k8 = t2 & 7;
            int n = t2 >> 3;
            uint32_t dst = SWZ((uint32_t)(n * 128 + 16 * k8));
            *(uint4*)(smem + SB_H + dst) =
                *(const uint4*)&Bh[(nBase + n) * DD + k0 + 8 * k8];
            *(uint4*)(smem + SB_L + dst) =
                *(const uint4*)&Bl[(nBase + n) * DD + k0 + 8 * k8];
        }
        __syncthreads();

#pragma unroll
        for (int kk = 0; kk < 4; kk++) {
            uint32_t kb = (uint32_t)(kk * 32);
            uint32_t aH[4][4], aL[4][4], bH[4][2], bL[4][2];
#pragma unroll
            for (int im = 0; im < 4; im++) {
                uint32_t ad = sb + SA_H + SWZ(aOff[im] + kb);
                LDSM_X4(aH[im][0], aH[im][1], aH[im][2], aH[im][3], ad);
                uint32_t al = sb + SA_L + SWZ(aOff[im] + kb);
                LDSM_X4(aL[im][0], aL[im][1], aL[im][2], aL[im][3], al);
            }
#pragma unroll
            for (int ip = 0; ip < 2; ip++) {
                uint32_t bd = sb + SB_H + SWZ(bOff[ip] + kb);
                LDSM_X4(bH[2 * ip][0], bH[2 * ip][1],
                        bH[2 * ip + 1][0], bH[2 * ip + 1][1], bd);
                uint32_t bl = sb + SB_L + SWZ(bOff[ip] + kb);
                LDSM_X4(bL[2 * ip][0], bL[2 * ip][1],
                        bL[2 * ip + 1][0], bL[2 * ip + 1][1], bl);
            }
#pragma unroll
            for (int im = 0; im < 4; im++)
#pragma unroll
                for (int jn = 0; jn < 4; jn++) {
                    MMA_BF16(acc[im][jn], aH[im], bH[jn]);
                    MMA_BF16(acc[im][jn], aH[im], bL[jn]);
                    MMA_BF16(acc[im][jn], aL[im], bH[jn]);
                }
        }
        __syncthreads();
    }

    // ---- epilogue: write accumulators straight to g_xl / g_xr ------------
    float* __restrict__ out = (colBase < 256) ? g_xl : g_xr;
    int cBase = nBase + warpN * 32;
#pragma unroll
    for (int im = 0; im < 4; im++) {
        int r0 = rowBase + warpM * 64 + im * 16 + (lane >> 2);
#pragma unroll
        for (int jn = 0; jn < 4; jn++) {
            int c = cBase + jn * 8 + (lane & 3) * 2;
            if (r0 < M)
                *(float2*)&out[r0 * DD + c] =
                    make_float2(acc[im][jn][0], acc[im][jn][1]);
            if (r0 + 8 < M)
                *(float2*)&out[(r0 + 8) * DD + c] =
                    make_float2(acc[im][jn][2], acc[im][jn][3]);
        }
    }
}

// ---------------- fused GATv2 aggregate + bias + LayerNorm + ReLU ---------
__global__ void __launch_bounds__(128)
gat_agg_kernel(const float* __restrict__ att, const float* __restrict__ bias,
               const float* __restrict__ gamma, const float* __restrict__ beta,
               float* __restrict__ ext_out, int write_ext) {
    int dst  = blockIdx.x;
    int warp = threadIdx.x >> 5;
    int lane = threadIdx.x & 31;
    int c0   = (warp << 6) + (lane << 1);

    float2 xrv  = *(const float2*)&g_xr[dst * DD + c0];
    float2 attv = *(const float2*)&att[c0];

    float m = -1e30f, lsum = 0.f;
    float accx = 0.f, accy = 0.f;

    int start = g_rowptr[dst];
    int end   = g_rowptr[dst + 1];
    for (int e = start - 1; e < end; e++) {
        int src = (e < start) ? dst : g_col[e];
        float2 xv = *(const float2*)&g_xl[src * DD + c0];
        float ax = xv.x + xrv.x;
        float ay = xv.y + xrv.y;
        ax = (ax > 0.f) ? ax : 0.2f * ax;
        ay = (ay > 0.f) ? ay : 0.2f * ay;
        float s = ax * attv.x + ay * attv.y;
#pragma unroll
        for (int off = 16; off; off >>= 1)
            s += __shfl_xor_sync(0xffffffffu, s, off);
        float nm = fmaxf(m, s);
        float sc = __expf(m - nm);
        float p  = __expf(s - nm);
        accx = accx * sc + p * xv.x;
        accy = accy * sc + p * xv.y;
        lsum = lsum * sc + p;
        m = nm;
    }
    float inv_l = 1.0f / lsum;
    float ox = accx * inv_l + bias[c0];
    float oy = accy * inv_l + bias[c0 + 1];

    float s1 = ox + oy;
    float s2 = ox * ox + oy * oy;
#pragma unroll
    for (int off = 16; off; off >>= 1) {
        s1 += __shfl_xor_sync(0xffffffffu, s1, off);
        s2 += __shfl_xor_sync(0xffffffffu, s2, off);
    }
    __shared__ float sh1[4], sh2[4];
    if (lane == 0) { sh1[warp] = s1; sh2[warp] = s2; }
    __syncthreads();
    s1 = sh1[0] + sh1[1] + sh1[2] + sh1[3];
    s2 = sh2[0] + sh2[1] + sh2[2] + sh2[3];
    float mean = s1 * (1.0f / DD);
    float var  = s2 * (1.0f / DD) - mean * mean;
    float rinv = rsqrtf(var + 1e-5f);

    ox = (ox - mean) * rinv * gamma[c0]     + beta[c0];
    oy = (oy - mean) * rinv * gamma[c0 + 1] + beta[c0 + 1];
    ox = fmaxf(ox, 0.f);
    oy = fmaxf(oy, 0.f);

    float* __restrict__ out = write_ext ? ext_out : g_h;
    *(float2*)&out[dst * DD + c0] = make_float2(ox, oy);
}

// ---------------- launch ---------------------------------------------------
extern "C" void kernel_launch(void* const* d_in, const int* in_sizes, int n_in,
                              void* d_out, int out_size) {
    const float* x  = (const float*)d_in[0];
    const int*   ei = (const int*)d_in[1];
    int E = in_sizes[1] / 2;          // 320000
    int N = in_sizes[0] / DD;         // 20000
    float* out = (float*)d_out;

    zero_deg_kernel<<<(N + 255) / 256, 256>>>(N);
    hist_kernel<<<(E + 255) / 256, 256>>>(ei, E);
    scan_kernel<<<1, 1024>>>(N);
    wptr_kernel<<<(N + 255) / 256, 256>>>(N);
    scatter_kernel<<<(E + 255) / 256, 256>>>(ei, E);

    static int smem_set = 0;
    if (!smem_set) {
        cudaFuncSetAttribute(gemm_kernel,
                             cudaFuncAttributeMaxDynamicSharedMemorySize,
                             GEMM_SMEM);
        smem_set = 1;
    }
    dim3 ggrid(4, (N + 127) / 128);   // 4 col-blocks of 128 over N=512

    for (int layer = 0; layer < 4; layer++) {
        const float* Wl  = (const float*)d_in[2 + 6 * layer + 0];
        const float* Wr  = (const float*)d_in[2 + 6 * layer + 1];
        const float* att = (const float*)d_in[2 + 6 * layer + 2];
        const float* b   = (const float*)d_in[2 + 6 * layer + 3];
        const float* g   = (const float*)d_in[2 + 6 * layer + 4];
        const float* be  = (const float*)d_in[2 + 6 * layer + 5];

        prep_w_kernel<<<dim3(8, 8, 2), dim3(32, 8)>>>(Wl, Wr);
        gemm_kernel<<<ggrid, 256, GEMM_SMEM>>>(x, layer == 0, N);
        gat_agg_kernel<<<N, 128>>>(att, b, g, be, out, layer == 3);
    }
}

// round 5
// speedup vs baseline: 1.8143x; 1.1103x over previous
#include <cuda_runtime.h>
#include <cuda_bf16.h>
#include <cstdint>

#define NN 20000
#define EE 320000
#define DD 256

// ---------------- scratch (static device globals; no allocation) ----------
__device__ float g_h [NN * DD];   // node features between layers
__device__ float g_xl[NN * DD];   // h @ Wl
__device__ float g_xr[NN * DD];   // h @ Wr
__device__ int   g_deg[NN];
__device__ int   g_rowptr[NN + 1];
__device__ int   g_wptr[NN];
__device__ int   g_col[EE];       // src indices sorted by dst (CSR)

// transposed, bf16-split weights for all layers: [2*layer + (0=Wl,1=Wr)]
__device__ __nv_bfloat16 g_Bh[8][DD * DD];
__device__ __nv_bfloat16 g_Bl[8][DD * DD];

// ---------------- helpers ---------------------------------------------------
__device__ __forceinline__ uint32_t smem_u32(const void* p) {
    uint32_t a;
    asm("{ .reg .u64 t; cvta.to.shared.u64 t, %1; cvt.u32.u64 %0, t; }"
        : "=r"(a) : "l"(p));
    return a;
}
#define SWZ(o) ((o) ^ (((o) >> 3) & 0x70))

#define LDSM_X4(r0, r1, r2, r3, a)                                          \
    asm volatile("ldmatrix.sync.aligned.m8n8.x4.shared.b16 {%0,%1,%2,%3}, [%4];" \
                 : "=r"(r0), "=r"(r1), "=r"(r2), "=r"(r3) : "r"(a))

#define MMA_BF16(d, a, b)                                                   \
    asm volatile("mma.sync.aligned.m16n8k16.row.col.f32.bf16.bf16.f32 "     \
                 "{%0,%1,%2,%3}, {%4,%5,%6,%7}, {%8,%9}, {%0,%1,%2,%3};"    \
                 : "+f"((d)[0]), "+f"((d)[1]), "+f"((d)[2]), "+f"((d)[3])   \
                 : "r"((a)[0]), "r"((a)[1]), "r"((a)[2]), "r"((a)[3]),      \
                   "r"((b)[0]), "r"((b)[1]))

#define CP_ASYNC16(dst, src)                                                \
    asm volatile("cp.async.cg.shared.global [%0], [%1], 16;"                \
                 :: "r"(dst), "l"(src) : "memory")
#define CP_COMMIT() asm volatile("cp.async.commit_group;" ::: "memory")
#define CP_WAIT(n)  asm volatile("cp.async.wait_group %0;" :: "n"(n) : "memory")

// ---------------- CSR build ----------------------------------------------
__global__ void zero_deg_kernel(int n) {
    int i = blockIdx.x * blockDim.x + threadIdx.x;
    if (i < n) g_deg[i] = 0;
}
__global__ void hist_kernel(const int* __restrict__ ei, int E) {
    int e = blockIdx.x * blockDim.x + threadIdx.x;
    if (e < E) atomicAdd(&g_deg[ei[E + e]], 1);
}
// exclusive scan; also writes g_wptr = rowptr[i]
__global__ void scan_kernel(int n) {
    __shared__ int sh[1024];
    __shared__ int carry;
    int t = threadIdx.x;
    if (t == 0) { carry = 0; g_rowptr[0] = 0; }
    __syncthreads();
    for (int base = 0; base < n; base += 1024) {
        int i = base + t;
        int v = (i < n) ? g_deg[i] : 0;
        sh[t] = v;
        __syncthreads();
        for (int off = 1; off < 1024; off <<= 1) {
            int tv = (t >= off) ? sh[t - off] : 0;
            __syncthreads();
            sh[t] += tv;
            __syncthreads();
        }
        if (i < n) {
            g_rowptr[i + 1] = carry + sh[t];
            g_wptr[i]       = carry + sh[t] - v;
        }
        __syncthreads();
        if (t == 0) carry += sh[1023];
        __syncthreads();
    }
}
__global__ void scatter_kernel(const int* __restrict__ ei, int E) {
    int e = blockIdx.x * blockDim.x + threadIdx.x;
    if (e < E) {
        int dst = ei[E + e];
        int pos = atomicAdd(&g_wptr[dst], 1);
        g_col[pos] = ei[e];
    }
}

// ---------------- weight transpose + bf16 hi/lo split (all 8 matrices) -----
__global__ void prep_all_kernel(const float* W0, const float* W1,
                                const float* W2, const float* W3,
                                const float* W4, const float* W5,
                                const float* W6, const float* W7) {
    __shared__ float t[32][33];
    const float* sel[8] = {W0, W1, W2, W3, W4, W5, W6, W7};
    int z = blockIdx.z;
    const float* W = sel[z];
    __nv_bfloat16* Oh = g_Bh[z];
    __nv_bfloat16* Ol = g_Bl[z];
    int bx = blockIdx.x * 32, by = blockIdx.y * 32;
    int tx = threadIdx.x, ty = threadIdx.y;       // 32 x 8
#pragma unroll
    for (int i = 0; i < 32; i += 8)
        t[ty + i][tx] = W[(by + ty + i) * DD + bx + tx];
    __syncthreads();
#pragma unroll
    for (int i = 0; i < 32; i += 8) {
        float v = t[tx][ty + i];
        __nv_bfloat16 h = __float2bfloat16_rn(v);
        __nv_bfloat16 l = __float2bfloat16_rn(v - __bfloat162float(h));
        int n = bx + ty + i, k = by + tx;
        Oh[n * DD + k] = h;
        Ol[n * DD + k] = l;
    }
}

// ---------------- mma.sync bf16x3 GEMM, cp.async pipelined ------------------
// C[M,512] = A[M,256] @ [Wl | Wr].  CTA: 128x128, 8 warps, K chunk 64.
// Smem: A_hi 16K | A_lo 16K | B double buffer 2 x (hi 16K + lo 16K) = 96K.
#define SA_H 0
#define SA_L 16384
#define SB0  32768
#define SB1  65536
#define GEMM_SMEM 98304

__global__ void __launch_bounds__(256, 1)
gemm_kernel(const float* __restrict__ Aext, int use_ext, int M, int layer) {
    extern __shared__ char smem[];
    uint32_t sb = smem_u32(smem);
    const float* __restrict__ A = use_ext ? Aext : g_h;

    int tid = threadIdx.x;
    int lane = tid & 31, wid = tid >> 5;
    int warpM = wid >> 2, warpN = wid & 3;
    int rowBase = blockIdx.y << 7;
    int colBase = blockIdx.x << 7;         // 0..511 in steps of 128

    int widx = layer * 2 + (colBase >= 256 ? 1 : 0);
    const __nv_bfloat16* __restrict__ Bh = g_Bh[widx];
    const __nv_bfloat16* __restrict__ Bl = g_Bl[widx];
    int nBase = colBase & 255;

    float acc[4][4][4];
#pragma unroll
    for (int i = 0; i < 4; i++)
#pragma unroll
        for (int j = 0; j < 4; j++)
#pragma unroll
            for (int q = 0; q < 4; q++) acc[i][j][q] = 0.f;

    // per-thread tile coords
    int a_k4  = tid & 15;                  // float4 index along k (A)
    int a_row = tid >> 4;                  // base row (stride 16 over 8 iters)
    int b_k8  = tid & 7;                   // 16B index along k (B)
    int b_n   = tid >> 3;                  // base n (stride 32 over 4 iters)

    // ldmatrix offsets
    uint32_t aOff[4], bOff[2];
#pragma unroll
    for (int im = 0; im < 4; im++)
        aOff[im] = (uint32_t)((warpM * 64 + im * 16 + (lane & 15)) * 128 +
                              (lane >> 4) * 16);
#pragma unroll
    for (int ip = 0; ip < 2; ip++)
        bOff[ip] = (uint32_t)((warpN * 32 + ip * 16 + ((lane >> 4) & 1) * 8 +
                               (lane & 7)) * 128 + ((lane >> 3) & 1) * 16);

    // ---- prologue: issue B(0) cp.async, load A(0) into regs ----
    float4 av[8];
    {
        uint32_t bufB = sb + SB0;
#pragma unroll
        for (int it = 0; it < 4; it++) {
            int n = b_n + it * 32;
            uint32_t dst = SWZ((uint32_t)(n * 128 + 16 * b_k8));
            CP_ASYNC16(bufB + dst,       (const void*)&Bh[(nBase + n) * DD + 8 * b_k8]);
            CP_ASYNC16(bufB + 16384 + dst, (const void*)&Bl[(nBase + n) * DD + 8 * b_k8]);
        }
        CP_COMMIT();
#pragma unroll
        for (int it = 0; it < 8; it++) {
            int row = a_row + it * 16;
            av[it] = (rowBase + row < M)
                ? *(const float4*)&A[(rowBase + row) * DD + 4 * a_k4]
                : make_float4(0.f, 0.f, 0.f, 0.f);
        }
    }

#pragma unroll
    for (int ch = 0; ch < 4; ch++) {
        // ---- store staged A regs -> smem (fp32 -> bf16 hi/lo) ----
#pragma unroll
        for (int it = 0; it < 8; it++) {
            int row = a_row + it * 16;
            float4 v = av[it];
            __nv_bfloat16 h0 = __float2bfloat16_rn(v.x);
            __nv_bfloat16 h1 = __float2bfloat16_rn(v.y);
            __nv_bfloat16 h2 = __float2bfloat16_rn(v.z);
            __nv_bfloat16 h3 = __float2bfloat16_rn(v.w);
            __nv_bfloat16 l0 = __float2bfloat16_rn(v.x - __bfloat162float(h0));
            __nv_bfloat16 l1 = __float2bfloat16_rn(v.y - __bfloat162float(h1));
            __nv_bfloat16 l2 = __float2bfloat16_rn(v.z - __bfloat162float(h2));
            __nv_bfloat16 l3 = __float2bfloat16_rn(v.w - __bfloat162float(h3));
            uint32_t hp0 = (uint32_t)__bfloat16_as_ushort(h0) |
                           ((uint32_t)__bfloat16_as_ushort(h1) << 16);
            uint32_t hp1 = (uint32_t)__bfloat16_as_ushort(h2) |
                           ((uint32_t)__bfloat16_as_ushort(h3) << 16);
            uint32_t lp0 = (uint32_t)__bfloat16_as_ushort(l0) |
                           ((uint32_t)__bfloat16_as_ushort(l1) << 16);
            uint32_t lp1 = (uint32_t)__bfloat16_as_ushort(l2) |
                           ((uint32_t)__bfloat16_as_ushort(l3) << 16);
            uint32_t off = SWZ((uint32_t)(row * 128 + 8 * a_k4));
            *(uint2*)(smem + SA_H + off) = make_uint2(hp0, hp1);
            *(uint2*)(smem + SA_L + off) = make_uint2(lp0, lp1);
        }
        // ---- issue next chunk's B cp.async + A reg prefetch ----
        if (ch < 3) {
            int k0n = (ch + 1) << 6;
            uint32_t bufB = sb + ((ch + 1) & 1 ? SB1 : SB0);
#pragma unroll
            for (int it = 0; it < 4; it++) {
                int n = b_n + it * 32;
                uint32_t dst = SWZ((uint32_t)(n * 128 + 16 * b_k8));
                CP_ASYNC16(bufB + dst,
                           (const void*)&Bh[(nBase + n) * DD + k0n + 8 * b_k8]);
                CP_ASYNC16(bufB + 16384 + dst,
                           (const void*)&Bl[(nBase + n) * DD + k0n + 8 * b_k8]);
            }
            CP_COMMIT();
#pragma unroll
            for (int it = 0; it < 8; it++) {
                int row = a_row + it * 16;
                av[it] = (rowBase + row < M)
                    ? *(const float4*)&A[(rowBase + row) * DD + k0n + 4 * a_k4]
                    : make_float4(0.f, 0.f, 0.f, 0.f);
            }
            CP_WAIT(1);              // B(ch) done, B(ch+1) may be in flight
        } else {
            CP_WAIT(0);
        }
        __syncthreads();             // A stores + B(ch) visible to all

        uint32_t sbB = sb + (ch & 1 ? SB1 : SB0);
#pragma unroll
        for (int kk = 0; kk < 4; kk++) {
            uint32_t kb = (uint32_t)(kk * 32);
            uint32_t aH[4][4], aL[4][4], bH[4][2], bL[4][2];
#pragma unroll
            for (int im = 0; im < 4; im++) {
                uint32_t ad = sb + SA_H + SWZ(aOff[im] + kb);
                LDSM_X4(aH[im][0], aH[im][1], aH[im][2], aH[im][3], ad);
                uint32_t al = sb + SA_L + SWZ(aOff[im] + kb);
                LDSM_X4(aL[im][0], aL[im][1], aL[im][2], aL[im][3], al);
            }
#pragma unroll
            for (int ip = 0; ip < 2; ip++) {
                uint32_t bd = sbB + SWZ(bOff[ip] + kb);
                LDSM_X4(bH[2 * ip][0], bH[2 * ip][1],
                        bH[2 * ip + 1][0], bH[2 * ip + 1][1], bd);
                uint32_t bl = sbB + 16384 + SWZ(bOff[ip] + kb);
                LDSM_X4(bL[2 * ip][0], bL[2 * ip][1],
                        bL[2 * ip + 1][0], bL[2 * ip + 1][1], bl);
            }
#pragma unroll
            for (int im = 0; im < 4; im++)
#pragma unroll
                for (int jn = 0; jn < 4; jn++) {
                    MMA_BF16(acc[im][jn], aH[im], bH[jn]);
                    MMA_BF16(acc[im][jn], aH[im], bL[jn]);
                    MMA_BF16(acc[im][jn], aL[im], bH[jn]);
                }
        }
        __syncthreads();             // before next chunk's A smem overwrite
    }

    // ---- epilogue ----------------------------------------------------------
    float* __restrict__ out = (colBase < 256) ? g_xl : g_xr;
    int cBase = nBase + warpN * 32;
#pragma unroll
    for (int im = 0; im < 4; im++) {
        int r0 = rowBase + warpM * 64 + im * 16 + (lane >> 2);
#pragma unroll
        for (int jn = 0; jn < 4; jn++) {
            int c = cBase + jn * 8 + (lane & 3) * 2;
            if (r0 < M)
                *(float2*)&out[r0 * DD + c] =
                    make_float2(acc[im][jn][0], acc[im][jn][1]);
            if (r0 + 8 < M)
                *(float2*)&out[(r0 + 8) * DD + c] =
                    make_float2(acc[im][jn][2], acc[im][jn][3]);
        }
    }
}

// ---------------- fused GATv2 aggregate + bias + LayerNorm + ReLU ---------
// Block = dst node, warp = head, 2 channels/lane. Edge loop unrolled by 2:
// two independent shuffle trees (ILP) + one combined online-softmax update.
__global__ void __launch_bounds__(128)
gat_agg_kernel(const float* __restrict__ att, const float* __restrict__ bias,
               const float* __restrict__ gamma, const float* __restrict__ beta,
               float* __restrict__ ext_out, int write_ext) {
    int dst  = blockIdx.x;
    int warp = threadIdx.x >> 5;
    int lane = threadIdx.x & 31;
    int c0   = (warp << 6) + (lane << 1);

    float2 xrv  = *(const float2*)&g_xr[dst * DD + c0];
    float2 attv = *(const float2*)&att[c0];

    // self loop initializes the running softmax state (p = 1)
    float2 xs = *(const float2*)&g_xl[dst * DD + c0];
    float ax = xs.x + xrv.x, ay = xs.y + xrv.y;
    ax = (ax > 0.f) ? ax : 0.2f * ax;
    ay = (ay > 0.f) ? ay : 0.2f * ay;
    float s = ax * attv.x + ay * attv.y;
#pragma unroll
    for (int off = 16; off; off >>= 1)
        s += __shfl_xor_sync(0xffffffffu, s, off);
    float m = s, lsum = 1.f;
    float accx = xs.x, accy = xs.y;

    int e   = g_rowptr[dst];
    int end = g_rowptr[dst + 1];
    for (; e + 1 < end; e += 2) {
        int i0 = g_col[e], i1 = g_col[e + 1];
        float2 x0 = *(const float2*)&g_xl[i0 * DD + c0];
        float2 x1 = *(const float2*)&g_xl[i1 * DD + c0];
        float a0x = x0.x + xrv.x, a0y = x0.y + xrv.y;
        float a1x = x1.x + xrv.x, a1y = x1.y + xrv.y;
        a0x = (a0x > 0.f) ? a0x : 0.2f * a0x;
        a0y = (a0y > 0.f) ? a0y : 0.2f * a0y;
        a1x = (a1x > 0.f) ? a1x : 0.2f * a1x;
        a1y = (a1y > 0.f) ? a1y : 0.2f * a1y;
        float s0 = a0x * attv.x + a0y * attv.y;
        float s1 = a1x * attv.x + a1y * attv.y;
#pragma unroll
        for (int off = 16; off; off >>= 1) {
            s0 += __shfl_xor_sync(0xffffffffu, s0, off);
            s1 += __shfl_xor_sync(0xffffffffu, s1, off);
        }
        float nm = fmaxf(m, fmaxf(s0, s1));
        float sc = __expf(m - nm);
        float p0 = __expf(s0 - nm);
        float p1 = __expf(s1 - nm);
        accx = accx * sc + p0 * x0.x + p1 * x1.x;
        accy = accy * sc + p0 * x0.y + p1 * x1.y;
        lsum = lsum * sc + p0 + p1;
        m = nm;
    }
    if (e < end) {
        int i0 = g_col[e];
        float2 x0 = *(const float2*)&g_xl[i0 * DD + c0];
        float a0x = x0.x + xrv.x, a0y = x0.y + xrv.y;
        a0x = (a0x > 0.f) ? a0x : 0.2f * a0x;
        a0y = (a0y > 0.f) ? a0y : 0.2f * a0y;
        float s0 = a0x * attv.x + a0y * attv.y;
#pragma unroll
        for (int off = 16; off; off >>= 1)
            s0 += __shfl_xor_sync(0xffffffffu, s0, off);
        float nm = fmaxf(m, s0);
        float sc = __expf(m - nm);
        float p0 = __expf(s0 - nm);
        accx = accx * sc + p0 * x0.x;
        accy = accy * sc + p0 * x0.y;
        lsum = lsum * sc + p0;
        m = nm;
    }

    float inv_l = 1.0f / lsum;
    float ox = accx * inv_l + bias[c0];
    float oy = accy * inv_l + bias[c0 + 1];

    float s1r = ox + oy;
    float s2r = ox * ox + oy * oy;
#pragma unroll
    for (int off = 16; off; off >>= 1) {
        s1r += __shfl_xor_sync(0xffffffffu, s1r, off);
        s2r += __shfl_xor_sync(0xffffffffu, s2r, off);
    }
    __shared__ float sh1[4], sh2[4];
    if (lane == 0) { sh1[warp] = s1r; sh2[warp] = s2r; }
    __syncthreads();
    s1r = sh1[0] + sh1[1] + sh1[2] + sh1[3];
    s2r = sh2[0] + sh2[1] + sh2[2] + sh2[3];
    float mean = s1r * (1.0f / DD);
    float var  = s2r * (1.0f / DD) - mean * mean;
    float rinv = rsqrtf(var + 1e-5f);

    ox = (ox - mean) * rinv * gamma[c0]     + beta[c0];
    oy = (oy - mean) * rinv * gamma[c0 + 1] + beta[c0 + 1];
    ox = fmaxf(ox, 0.f);
    oy = fmaxf(oy, 0.f);

    float* __restrict__ out = write_ext ? ext_out : g_h;
    *(float2*)&out[dst * DD + c0] = make_float2(ox, oy);
}

// ---------------- launch ---------------------------------------------------
extern "C" void kernel_launch(void* const* d_in, const int* in_sizes, int n_in,
                              void* d_out, int out_size) {
    const float* x  = (const float*)d_in[0];
    const int*   ei = (const int*)d_in[1];
    int E = in_sizes[1] / 2;          // 320000
    int N = in_sizes[0] / DD;         // 20000
    float* out = (float*)d_out;

    zero_deg_kernel<<<(N + 255) / 256, 256>>>(N);                 // launch 0
    hist_kernel<<<(E + 255) / 256, 256>>>(ei, E);                 // 1
    scan_kernel<<<1, 1024>>>(N);                                  // 2
    scatter_kernel<<<(E + 255) / 256, 256>>>(ei, E);              // 3

    prep_all_kernel<<<dim3(8, 8, 8), dim3(32, 8)>>>(              // 4
        (const float*)d_in[2],  (const float*)d_in[3],
        (const float*)d_in[8],  (const float*)d_in[9],
        (const float*)d_in[14], (const float*)d_in[15],
        (const float*)d_in[20], (const float*)d_in[21]);

    static int smem_set = 0;
    if (!smem_set) {
        cudaFuncSetAttribute(gemm_kernel,
                             cudaFuncAttributeMaxDynamicSharedMemorySize,
                             GEMM_SMEM);
        smem_set = 1;
    }
    dim3 ggrid(4, (N + 127) / 128);

    for (int layer = 0; layer < 4; layer++) {
        const float* att = (const float*)d_in[2 + 6 * layer + 2];
        const float* b   = (const float*)d_in[2 + 6 * layer + 3];
        const float* g   = (const float*)d_in[2 + 6 * layer + 4];
        const float* be  = (const float*)d_in[2 + 6 * layer + 5];

        gemm_kernel<<<ggrid, 256, GEMM_SMEM>>>(x, layer == 0, N, layer); // 5, 7, 9, 11
        gat_agg_kernel<<<N, 128>>>(att, b, g, be, out, layer == 3);      // 6, 8, 10, 12
    }
}